// round 7
// baseline (speedup 1.0000x reference)
#include <cuda_runtime.h>

#define BATCH 8
#define HH 480
#define WW 640
#define PLANE (HH * WW)
#define NPIX (BATCH * PLANE)
#define TIMES 24
#define TFUSE 8
#define NLAUNCH (TIMES / TFUSE)   // 3

#define TILE_X 32
#define TILE_Y 24
#define OFF  (TFUSE - 1)          // 7 : inner tile at region rows 7..30
#define CROWS (TILE_Y + 2 * OFF)  // 38 computed rows: gy = oy-7 .. oy+30
#define NGRP 12                   // 12 groups of 4: gx = ox-8 .. ox+39
#define NACT (CROWS * NGRP)       // 456 active threads
#define BROWS 40                  // buffer rows: gy = oy-8 .. oy+31
#define BSTR 56                   // buffer cols: gx = ox-12 .. ox+43
#define NTHREADS 512

// Scratch (allocation-free rule: __device__ globals)
__device__ float g_buf0[NPIX];
__device__ float g_buf1[NPIX];

// ---------------------------------------------------------------------------
// Fused kernel: per-thread affinity load + normalize -> 9 tap weights in regs,
// then TFUSE propagation steps ping-ponging a 40x56 window in smem.
// 512 threads, 2 CTAs/SM for load/compute overlap across co-resident CTAs.
// ---------------------------------------------------------------------------
__global__ void __launch_bounds__(NTHREADS, 2)
fused_kernel(const float* __restrict__ affinity,
             const float* __restrict__ fin, float* __restrict__ fout) {
    __shared__ __align__(16) float buf[2][BROWS * BSTR];

    const int tid = threadIdx.x;
    const int ox = blockIdx.x * TILE_X;
    const int oy = blockIdx.y * TILE_Y;
    const int b  = blockIdx.z;

    // ---- load feature window; full into buf0, static ring into buf1 ----
    const float* src = fin + (size_t)b * PLANE;
#pragma unroll
    for (int idx = tid; idx < BROWS * BSTR; idx += NTHREADS) {
        const int br = idx / BSTR, bc = idx % BSTR;
        const int gy = oy - 8  + br;      // buffer row br <-> region row br-1
        const int gx = ox - 12 + bc;      // buffer col bc <-> region col bc-4
        float v = 0.f;
        if (gy >= 0 && gy < HH && gx >= 0 && gx < WW)
            v = __ldg(src + gy * WW + gx);
        buf[0][idx] = v;
        if (br == 0 || br == BROWS - 1 || bc < 4 || bc > 51)
            buf[1][idx] = v;              // ring (never recomputed)
    }

    // ---- per-thread: 8 affinity float4 LDGs, normalize -> 9 tap weights ----
    const bool active = (tid < NACT);
    const int row  = tid / NGRP;          // region row 0..37
    const int grp  = tid % NGRP;
    const int col0 = grp * 4;
    const int gy   = oy - OFF + row;
    const int gx0  = ox - 8 + col0;       // 4-aligned

    float4 w4[9];
    {
        const bool ok = active && gy >= 0 && gy < HH && gx0 >= 0 && gx0 < WW;
        const float4 z = make_float4(0.f, 0.f, 0.f, 0.f);
        if (ok) {
            const float* ab = affinity + (size_t)b * 8 * PLANE + gy * WW + gx0;
            float4 a[8];
            float4 s = z;
#pragma unroll
            for (int c = 0; c < 8; c++) {
                a[c] = __ldg((const float4*)(ab + (size_t)c * PLANE));
                s.x += fabsf(a[c].x); s.y += fabsf(a[c].y);
                s.z += fabsf(a[c].z); s.w += fabsf(a[c].w);
            }
            const float4 inv = make_float4(1.f/s.x, 1.f/s.y, 1.f/s.z, 1.f/s.w);
            float4 ns = z;
#pragma unroll
            for (int c = 0; c < 8; c++) {
                a[c].x *= inv.x; a[c].y *= inv.y;
                a[c].z *= inv.z; a[c].w *= inv.w;
                ns.x += a[c].x; ns.y += a[c].y;
                ns.z += a[c].z; ns.w += a[c].w;
            }
#pragma unroll
            for (int c = 0; c < 4; c++) w4[c] = a[c];
            w4[4] = make_float4(1.f - ns.x, 1.f - ns.y, 1.f - ns.z, 1.f - ns.w);
#pragma unroll
            for (int c = 4; c < 8; c++) w4[c + 1] = a[c];
        } else {
#pragma unroll
            for (int k = 0; k < 9; k++) w4[k] = z;
        }
    }
    __syncthreads();

    // ---- TFUSE fused iterations ----
    const int bcol = col0 + 4;            // aligned buffer col of output group
    float a0, a1, a2, a3;
    int cur = 0;
#pragma unroll
    for (int t = 0; t < TFUSE; t++) {
        const float* s = buf[cur];
        if (active) {
            a0 = a1 = a2 = a3 = 0.f;
#pragma unroll
            for (int rr = 0; rr < 3; rr++) {
                const float* sp = s + (row + rr) * BSTR + bcol;
                const float2 lv = *(const float2*)(sp - 2);   // .y = bcol-1
                const float4 cv = *(const float4*)(sp);
                const float2 rv = *(const float2*)(sp + 4);   // .x = bcol+4
                const float f0 = lv.y, f1 = cv.x, f2 = cv.y,
                            f3 = cv.z, f4 = cv.w, f5 = rv.x;
                const float4 wa = w4[3 * rr + 0];
                const float4 wb = w4[3 * rr + 1];
                const float4 wc = w4[3 * rr + 2];
                a0 = fmaf(wa.x, f0, fmaf(wb.x, f1, fmaf(wc.x, f2, a0)));
                a1 = fmaf(wa.y, f1, fmaf(wb.y, f2, fmaf(wc.y, f3, a1)));
                a2 = fmaf(wa.z, f2, fmaf(wb.z, f3, fmaf(wc.z, f4, a2)));
                a3 = fmaf(wa.w, f3, fmaf(wb.w, f4, fmaf(wc.w, f5, a3)));
            }
            if (t < TFUSE - 1) {
                float* dp = buf[cur ^ 1] + (row + 1) * BSTR + bcol;
                *(float4*)dp = make_float4(a0, a1, a2, a3);    // STS.128
            }
        }
        if (t < TFUSE - 1) __syncthreads();
        cur ^= 1;
    }

    // ---- final: inner 32x24 straight from registers (STG.128) ----
    if (active && row >= OFF && row < OFF + TILE_Y && grp >= 2 && grp < 10) {
        float* out = fout + (size_t)b * PLANE;
        *(float4*)(out + gy * WW + gx0) = make_float4(a0, a1, a2, a3);
    }
}

// ---------------------------------------------------------------------------
extern "C" void kernel_launch(void* const* d_in, const int* in_sizes, int n_in,
                              void* d_out, int out_size) {
    const float* affinity = (const float*)d_in[0];
    const float* feature  = (const float*)d_in[1];
    float* out = (float*)d_out;

    void* p0 = nullptr; void* p1 = nullptr;
    cudaGetSymbolAddress(&p0, g_buf0);
    cudaGetSymbolAddress(&p1, g_buf1);
    float* buf[2] = { (float*)p0, (float*)p1 };

    dim3 fblk(NTHREADS, 1, 1);
    dim3 fgrd(WW / TILE_X, HH / TILE_Y, BATCH);   // 20 x 20 x 8

    const float* cursrc = feature;
    for (int l = 0; l < NLAUNCH; l++) {
        float* dst = (l == NLAUNCH - 1) ? out : buf[l & 1];
        fused_kernel<<<fgrd, fblk>>>(affinity, cursrc, dst);
        cursrc = dst;
    }
    (void)in_sizes; (void)n_in; (void)out_size;
}

// round 8
// speedup vs baseline: 1.3967x; 1.3967x over previous
#include <cuda_runtime.h>

#define BATCH 8
#define HH 480
#define WW 640
#define PLANE (HH * WW)
#define NPIX (BATCH * PLANE)
#define TIMES 24
#define TFUSE 8
#define NLAUNCH (TIMES / TFUSE)   // 3

#define TILE_X 64
#define TILE_Y 32
#define OFF  (TFUSE - 1)          // 7
#define CROWS 46                  // computed rows: gy = oy-7 .. oy+38
#define NGRP 20                   // groups of 4: gx = ox-8 .. ox+71
#define NACT (CROWS * NGRP)       // 920
#define BROWS 48                  // buffer rows: gy = oy-8 .. oy+39
#define BSTR 92                   // buffer cols: gx = ox-12 .. ox+79
#define NTHREADS 1024
#define NF4 (BROWS * (BSTR / 4))  // 48*23 = 1104 float4s per buffer

// Scratch (allocation-free rule: __device__ globals)
__device__ float g_buf0[NPIX];
__device__ float g_buf1[NPIX];

// ---------------------------------------------------------------------------
__global__ void __launch_bounds__(NTHREADS, 1)
fused_kernel(const float* __restrict__ affinity,
             const float* __restrict__ fin, float* __restrict__ fout) {
    __shared__ __align__(16) float buf[2][BROWS * BSTR];

    const int tid  = threadIdx.x;
    const int lane = tid & 31;
    const int ox = blockIdx.x * TILE_X;
    const int oy = blockIdx.y * TILE_Y;
    const int b  = blockIdx.z;

    const bool active = (tid < NACT);
    const int row  = tid / NGRP;           // region row (garbage-safe if !active)
    const int grp  = tid % NGRP;
    const int col0 = grp * 4;
    const int crow = active ? row : 0;     // clamped row for smem addressing
    const int gy   = oy - OFF + row;
    const int gx0  = ox - 8 + col0;        // 4-aligned

    // ---- per-thread: 8 affinity float4 LDGs, normalize -> 9 tap weights ----
    float4 w4[9];
    {
        const bool ok = active && gy >= 0 && gy < HH && gx0 >= 0 && gx0 < WW;
        const float4 z = make_float4(0.f, 0.f, 0.f, 0.f);
        if (ok) {
            const float* ab = affinity + (size_t)b * 8 * PLANE + gy * WW + gx0;
            float4 a[8];
            float4 s = z;
#pragma unroll
            for (int c = 0; c < 8; c++) {
                a[c] = __ldg((const float4*)(ab + (size_t)c * PLANE));
                s.x += fabsf(a[c].x); s.y += fabsf(a[c].y);
                s.z += fabsf(a[c].z); s.w += fabsf(a[c].w);
            }
            const float4 inv = make_float4(1.f/s.x, 1.f/s.y, 1.f/s.z, 1.f/s.w);
            float4 ns = z;
#pragma unroll
            for (int c = 0; c < 8; c++) {
                a[c].x *= inv.x; a[c].y *= inv.y;
                a[c].z *= inv.z; a[c].w *= inv.w;
                ns.x += a[c].x; ns.y += a[c].y;
                ns.z += a[c].z; ns.w += a[c].w;
            }
#pragma unroll
            for (int c = 0; c < 4; c++) w4[c] = a[c];
            w4[4] = make_float4(1.f - ns.x, 1.f - ns.y, 1.f - ns.z, 1.f - ns.w);
#pragma unroll
            for (int c = 4; c < 8; c++) w4[c + 1] = a[c];
        } else {
#pragma unroll
            for (int k = 0; k < 9; k++) w4[k] = z;
        }
    }

    // ---- vectorized feature-window load into BOTH buffers ----
    // WW % 4 == 0 and all float4s are 4-aligned -> each float4 is fully
    // in-image or fully out (zero). No partial lanes.
    const float* src = fin + (size_t)b * PLANE;
#pragma unroll
    for (int it = 0; it < 2; it++) {
        const int idx = tid + it * NTHREADS;
        if (idx < NF4) {
            const int br  = idx / (BSTR / 4);
            const int bc4 = idx % (BSTR / 4);
            const int gyw = oy - 8 + br;
            const int gxw = ox - 12 + bc4 * 4;
            float4 v = make_float4(0.f, 0.f, 0.f, 0.f);
            if (gyw >= 0 && gyw < HH && gxw >= 0 && gxw < WW)
                v = __ldg((const float4*)(src + gyw * WW + gxw));
            ((float4*)&buf[0][br * BSTR])[bc4] = v;
            ((float4*)&buf[1][br * BSTR])[bc4] = v;
        }
    }
    __syncthreads();

    // ---- TFUSE fused iterations (shfl-assisted horizontal taps) ----
    const int  bcol  = col0 + 4;                 // aligned buffer col
    const bool needL = (grp == 0)        || (lane == 0);
    const bool needR = (grp == NGRP - 1) || (lane == 31);
    float a0, a1, a2, a3;
    int cur = 0;
#pragma unroll
    for (int t = 0; t < TFUSE; t++) {
        const float* s = buf[cur];
        a0 = a1 = a2 = a3 = 0.f;
#pragma unroll
        for (int rr = 0; rr < 3; rr++) {
            const float* sp = s + (crow + rr) * BSTR + bcol;
            const float4 cv = *(const float4*)sp;        // LDS.128
            float f0 = __shfl_up_sync(0xffffffffu, cv.w, 1);
            float f5 = __shfl_down_sync(0xffffffffu, cv.x, 1);
            if (needL) f0 = sp[-1];
            if (needR) f5 = sp[4];
            const float4 wa = w4[3 * rr + 0];
            const float4 wb = w4[3 * rr + 1];
            const float4 wc = w4[3 * rr + 2];
            a0 = fmaf(wa.x, f0,   fmaf(wb.x, cv.x, fmaf(wc.x, cv.y, a0)));
            a1 = fmaf(wa.y, cv.x, fmaf(wb.y, cv.y, fmaf(wc.y, cv.z, a1)));
            a2 = fmaf(wa.z, cv.y, fmaf(wb.z, cv.z, fmaf(wc.z, cv.w, a2)));
            a3 = fmaf(wa.w, cv.z, fmaf(wb.w, cv.w, fmaf(wc.w, f5,   a3)));
        }
        if (t < TFUSE - 1) {
            if (active) {
                float* dp = buf[cur ^ 1] + (crow + 1) * BSTR + bcol;
                *(float4*)dp = make_float4(a0, a1, a2, a3);   // STS.128
            }
            __syncthreads();
        }
        cur ^= 1;
    }

    // ---- final: inner 64x32 straight from registers (STG.128) ----
    if (active && row >= OFF && row < OFF + TILE_Y && grp >= 2 && grp < 18) {
        float* out = fout + (size_t)b * PLANE;
        *(float4*)(out + gy * WW + gx0) = make_float4(a0, a1, a2, a3);
    }
}

// ---------------------------------------------------------------------------
extern "C" void kernel_launch(void* const* d_in, const int* in_sizes, int n_in,
                              void* d_out, int out_size) {
    const float* affinity = (const float*)d_in[0];
    const float* feature  = (const float*)d_in[1];
    float* out = (float*)d_out;

    void* p0 = nullptr; void* p1 = nullptr;
    cudaGetSymbolAddress(&p0, g_buf0);
    cudaGetSymbolAddress(&p1, g_buf1);
    float* buf[2] = { (float*)p0, (float*)p1 };

    dim3 fblk(NTHREADS, 1, 1);
    dim3 fgrd(WW / TILE_X, HH / TILE_Y, BATCH);   // 10 x 15 x 8

    const float* cursrc = feature;
    for (int l = 0; l < NLAUNCH; l++) {
        float* dst = (l == NLAUNCH - 1) ? out : buf[l & 1];
        fused_kernel<<<fgrd, fblk>>>(affinity, cursrc, dst);
        cursrc = dst;
    }
    (void)in_sizes; (void)n_in; (void)out_size;
}

// round 9
// speedup vs baseline: 1.4647x; 1.0486x over previous
#include <cuda_runtime.h>

#define BATCH 8
#define HH 480
#define WW 640
#define PLANE (HH * WW)
#define NPIX (BATCH * PLANE)
#define TIMES 24
#define TFUSE 8
#define NLAUNCH (TIMES / TFUSE)   // 3

#define TILE_X 64
#define TILE_Y 32
#define OFF  (TFUSE - 1)          // 7
#define CROWS 46                  // computed rows: gy = oy-7 .. oy+38
#define NGRP 20                   // groups of 4: gx = ox-8 .. ox+71
#define NACT (CROWS * NGRP)       // 920
#define NLOOP 928                 // loop-resident threads (29 warps)
#define BROWS 48                  // buffer rows: gy = oy-8 .. oy+39
#define BSTR 92                   // buffer cols: gx = ox-12 .. ox+79
#define NTHREADS 1024
#define NF4 (BROWS * (BSTR / 4))  // 1104 float4s per buffer

// Scratch (allocation-free rule: __device__ globals)
__device__ float g_buf0[NPIX];
__device__ float g_buf1[NPIX];

// ---------------------------------------------------------------------------
__global__ void __launch_bounds__(NTHREADS, 1)
fused_kernel(const float* __restrict__ affinity,
             const float* __restrict__ fin, float* __restrict__ fout) {
    __shared__ __align__(16) float buf[2][BROWS * BSTR];

    const int tid  = threadIdx.x;
    const int lane = tid & 31;
    const int ox = blockIdx.x * TILE_X;
    const int oy = blockIdx.y * TILE_Y;
    const int b  = blockIdx.z;

    const bool active = (tid < NACT);
    const int row  = tid / NGRP;
    const int grp  = tid % NGRP;
    const int col0 = grp * 4;
    const int crow = active ? row : 0;
    const int gy   = oy - OFF + row;
    const int gx0  = ox - 8 + col0;        // 4-aligned

    const float4 z4 = make_float4(0.f, 0.f, 0.f, 0.f);

    // ---- issue ALL independent global loads up-front (max MLP) ----
    // window float4 #1 (all threads) and #2 (tid < 80)
    const float* src = fin + (size_t)b * PLANE;
    const int br0  = tid / (BSTR / 4);
    const int bc40 = tid % (BSTR / 4);
    const int gy0  = oy - 8 + br0;
    const int gx0w = ox - 12 + bc40 * 4;
    float4 v0 = z4;
    if (gy0 >= 0 && gy0 < HH && gx0w >= 0 && gx0w < WW)
        v0 = __ldg((const float4*)(src + gy0 * WW + gx0w));

    const int idx1 = tid + NTHREADS;
    const int br1  = idx1 / (BSTR / 4);
    const int bc41 = idx1 % (BSTR / 4);
    const int gy1  = oy - 8 + br1;
    const int gx1w = ox - 12 + bc41 * 4;
    float4 v1 = z4;
    if (idx1 < NF4 && gy1 >= 0 && gy1 < HH && gx1w >= 0 && gx1w < WW)
        v1 = __ldg((const float4*)(src + gy1 * WW + gx1w));

    // affinity: 8 float4 LDGs (in flight together with window loads)
    const bool ok = active && gy >= 0 && gy < HH && gx0 >= 0 && gx0 < WW;
    float4 a[8];
    {
        const float* ab = affinity + (size_t)b * 8 * PLANE + gy * WW + gx0;
#pragma unroll
        for (int c = 0; c < 8; c++)
            a[c] = ok ? __ldg((const float4*)(ab + (size_t)c * PLANE)) : z4;
    }

    // ---- store window: full buf0, ring-only buf1 ----
    {
        ((float4*)&buf[0][br0 * BSTR])[bc40] = v0;
        if (br0 == 0 || br0 == BROWS - 1 || bc40 == 0 || bc40 >= 21)
            ((float4*)&buf[1][br0 * BSTR])[bc40] = v0;
        if (idx1 < NF4) {
            ((float4*)&buf[0][br1 * BSTR])[bc41] = v1;
            if (br1 == 0 || br1 == BROWS - 1 || bc41 == 0 || bc41 >= 21)
                ((float4*)&buf[1][br1 * BSTR])[bc41] = v1;
        }
    }

    // ---- normalize -> 9 tap weights (register-local; overlaps others' loads)
    float4 w4[9];
    {
        float4 s = z4;
#pragma unroll
        for (int c = 0; c < 8; c++) {
            s.x += fabsf(a[c].x); s.y += fabsf(a[c].y);
            s.z += fabsf(a[c].z); s.w += fabsf(a[c].w);
        }
        const float4 inv = ok ? make_float4(1.f/s.x, 1.f/s.y, 1.f/s.z, 1.f/s.w) : z4;
        float4 ns = z4;
#pragma unroll
        for (int c = 0; c < 8; c++) {
            a[c].x *= inv.x; a[c].y *= inv.y;
            a[c].z *= inv.z; a[c].w *= inv.w;
            ns.x += a[c].x; ns.y += a[c].y;
            ns.z += a[c].z; ns.w += a[c].w;
        }
#pragma unroll
        for (int c = 0; c < 4; c++) w4[c] = a[c];
        w4[4] = ok ? make_float4(1.f - ns.x, 1.f - ns.y, 1.f - ns.z, 1.f - ns.w) : z4;
#pragma unroll
        for (int c = 4; c < 8; c++) w4[c + 1] = a[c];
    }

    __syncthreads();                 // all 1024: window visible
    if (tid >= NLOOP) return;        // warps 29-31 retire

    // ---- TFUSE fused iterations (29 warps, named barrier) ----
    const int  bcol  = col0 + 4;
    const bool needL = (grp == 0)        || (lane == 0);
    const bool needR = (grp == NGRP - 1) || (lane == 31);
    float a0, a1, a2, a3;
    int cur = 0;
#pragma unroll
    for (int t = 0; t < TFUSE; t++) {
        const float* s = buf[cur];
        a0 = a1 = a2 = a3 = 0.f;
#pragma unroll
        for (int rr = 0; rr < 3; rr++) {
            const float* sp = s + (crow + rr) * BSTR + bcol;
            const float4 cv = *(const float4*)sp;        // LDS.128
            float f0 = __shfl_up_sync(0xffffffffu, cv.w, 1);
            float f5 = __shfl_down_sync(0xffffffffu, cv.x, 1);
            if (needL) f0 = sp[-1];
            if (needR) f5 = sp[4];
            const float4 wa = w4[3 * rr + 0];
            const float4 wb = w4[3 * rr + 1];
            const float4 wc = w4[3 * rr + 2];
            a0 = fmaf(wa.x, f0,   fmaf(wb.x, cv.x, fmaf(wc.x, cv.y, a0)));
            a1 = fmaf(wa.y, cv.x, fmaf(wb.y, cv.y, fmaf(wc.y, cv.z, a1)));
            a2 = fmaf(wa.z, cv.y, fmaf(wb.z, cv.z, fmaf(wc.z, cv.w, a2)));
            a3 = fmaf(wa.w, cv.z, fmaf(wb.w, cv.w, fmaf(wc.w, f5,   a3)));
        }
        if (t < TFUSE - 1) {
            if (active) {
                float* dp = buf[cur ^ 1] + (crow + 1) * BSTR + bcol;
                *(float4*)dp = make_float4(a0, a1, a2, a3);   // STS.128
            }
            asm volatile("bar.sync 1, %0;" :: "r"(NLOOP) : "memory");
        }
        cur ^= 1;
    }

    // ---- final: inner 64x32 straight from registers (STG.128) ----
    if (active && row >= OFF && row < OFF + TILE_Y && grp >= 2 && grp < 18) {
        float* out = fout + (size_t)b * PLANE;
        *(float4*)(out + gy * WW + gx0) = make_float4(a0, a1, a2, a3);
    }
}

// ---------------------------------------------------------------------------
extern "C" void kernel_launch(void* const* d_in, const int* in_sizes, int n_in,
                              void* d_out, int out_size) {
    const float* affinity = (const float*)d_in[0];
    const float* feature  = (const float*)d_in[1];
    float* out = (float*)d_out;

    void* p0 = nullptr; void* p1 = nullptr;
    cudaGetSymbolAddress(&p0, g_buf0);
    cudaGetSymbolAddress(&p1, g_buf1);
    float* buf[2] = { (float*)p0, (float*)p1 };

    dim3 fblk(NTHREADS, 1, 1);
    dim3 fgrd(WW / TILE_X, HH / TILE_Y, BATCH);   // 10 x 15 x 8

    const float* cursrc = feature;
    for (int l = 0; l < NLAUNCH; l++) {
        float* dst = (l == NLAUNCH - 1) ? out : buf[l & 1];
        fused_kernel<<<fgrd, fblk>>>(affinity, cursrc, dst);
        cursrc = dst;
    }
    (void)in_sizes; (void)n_in; (void)out_size;
}

// round 10
// speedup vs baseline: 1.5378x; 1.0499x over previous
#include <cuda_runtime.h>

#define BATCH 8
#define HH 480
#define WW 640
#define PLANE (HH * WW)
#define NPIX (BATCH * PLANE)
#define TIMES 24
#define TFUSE 8
#define NLAUNCH (TIMES / TFUSE)   // 3

#define TILE_X 40
#define TILE_Y 48
#define OFF  7                    // inner tile: region rows 7..54, cols 8..47
#define NGRP 16                   // 16 groups of 4 cols: region cols 0..63 (gx = ox-8 .. ox+55)
#define BROWS 64                  // buffer rows: gy = oy-8 .. oy+55
#define BSTR 72                   // buffer cols 0..71; region col c -> buffer col c+4; ring at 3 / 68
#define NTHREADS 992              // 31 warps; warp = 2 rows x 16 groups
#define NF4 (BROWS * (BSTR / 4))  // 64*18 = 1152 float4s per buffer

// Scratch (allocation-free rule: __device__ globals)
__device__ float g_buf0[NPIX];
__device__ float g_buf1[NPIX];

// ---------------------------------------------------------------------------
__global__ void __launch_bounds__(NTHREADS, 1)
fused_kernel(const float* __restrict__ affinity,
             const float* __restrict__ fin, float* __restrict__ fout) {
    __shared__ __align__(16) float buf[2][BROWS * BSTR];

    const int tid  = threadIdx.x;
    const int lane = tid & 31;
    const int grp  = lane & 15;                       // col group 0..15
    const int row  = ((tid >> 5) << 1) + (lane >> 4); // region row 0..61
    const int ox = blockIdx.x * TILE_X;
    const int oy = blockIdx.y * TILE_Y;
    const int b  = blockIdx.z;

    const int gy  = oy - OFF + row;       // region row r <-> gy = oy-7+r
    const int gx0 = ox - 8 + grp * 4;     // 4-aligned

    const float4 z4 = make_float4(0.f, 0.f, 0.f, 0.f);

    // ---- issue all independent global loads up-front (MLP) ----
    const float* src = fin + (size_t)b * PLANE;
    const int br0 = tid / 18, bc40 = tid % 18;
    const int gyw0 = oy - 8 + br0, gxw0 = ox - 12 + bc40 * 4;
    float4 v0 = z4;
    if (gyw0 >= 0 && gyw0 < HH && gxw0 >= 0 && gxw0 < WW)
        v0 = __ldg((const float4*)(src + gyw0 * WW + gxw0));

    const int idx1 = tid + NTHREADS;
    const int br1 = idx1 / 18, bc41 = idx1 % 18;
    float4 v1 = z4;
    if (idx1 < NF4) {
        const int gyw1 = oy - 8 + br1, gxw1 = ox - 12 + bc41 * 4;
        if (gyw1 >= 0 && gyw1 < HH && gxw1 >= 0 && gxw1 < WW)
            v1 = __ldg((const float4*)(src + gyw1 * WW + gxw1));
    }

    // affinity: 8 float4 LDGs (grps 14/15 are beyond the influence horizon -> skip)
    const bool ok = (grp < 14) && gy >= 0 && gy < HH && gx0 >= 0 && gx0 < WW;
    float4 a[8];
    {
        const float* ab = affinity + (size_t)b * 8 * PLANE + gy * WW + gx0;
#pragma unroll
        for (int c = 0; c < 8; c++)
            a[c] = ok ? __ldg((const float4*)(ab + (size_t)c * PLANE)) : z4;
    }

    // ---- store window: full buf0, ring-only buf1 ----
    ((float4*)&buf[0][br0 * BSTR])[bc40] = v0;
    if (br0 == 0 || br0 == BROWS - 1 || bc40 == 0 || bc40 == 17)
        ((float4*)&buf[1][br0 * BSTR])[bc40] = v0;
    if (idx1 < NF4) {
        ((float4*)&buf[0][br1 * BSTR])[bc41] = v1;
        if (br1 == 0 || br1 == BROWS - 1 || bc41 == 0 || bc41 == 17)
            ((float4*)&buf[1][br1 * BSTR])[bc41] = v1;
    }

    // ---- normalize -> 9 tap weights ----
    float4 w4[9];
    {
        float4 s = z4;
#pragma unroll
        for (int c = 0; c < 8; c++) {
            s.x += fabsf(a[c].x); s.y += fabsf(a[c].y);
            s.z += fabsf(a[c].z); s.w += fabsf(a[c].w);
        }
        const float4 inv = ok ? make_float4(1.f/s.x, 1.f/s.y, 1.f/s.z, 1.f/s.w) : z4;
        float4 ns = z4;
#pragma unroll
        for (int c = 0; c < 8; c++) {
            a[c].x *= inv.x; a[c].y *= inv.y;
            a[c].z *= inv.z; a[c].w *= inv.w;
            ns.x += a[c].x; ns.y += a[c].y;
            ns.z += a[c].z; ns.w += a[c].w;
        }
#pragma unroll
        for (int c = 0; c < 4; c++) w4[c] = a[c];
        w4[4] = ok ? make_float4(1.f - ns.x, 1.f - ns.y, 1.f - ns.z, 1.f - ns.w) : z4;
#pragma unroll
        for (int c = 4; c < 8; c++) w4[c + 1] = a[c];
    }

    __syncthreads();

    // ---- hoist static ring values (cols never recomputed) ----
    const bool isL = (grp == 0), isR = (grp == 15);
    float ringL[3] = {0.f, 0.f, 0.f}, ringR[3] = {0.f, 0.f, 0.f};
    if (isL) {
#pragma unroll
        for (int r = 0; r < 3; r++) ringL[r] = buf[0][(row + r) * BSTR + 3];
    }
    if (isR) {
#pragma unroll
        for (int r = 0; r < 3; r++) ringR[r] = buf[0][(row + r) * BSTR + 68];
    }

    // ---- TFUSE fused iterations: 2 LDS.128 + carry + shfl only ----
    const int bcol = grp * 4 + 4;
    float c0 = 0.f, c1 = 0.f, c2 = 0.f, c3 = 0.f;   // carried own-row values
    float a0, a1, a2, a3;
    int cur = 0;
#pragma unroll
    for (int t = 0; t < TFUSE; t++) {
        const float* s = buf[cur];
        const float4 r0 = *(const float4*)(s + row * BSTR + bcol);
        float4 r1;
        if (t == 0) r1 = *(const float4*)(s + (row + 1) * BSTR + bcol);
        else        r1 = make_float4(c0, c1, c2, c3);
        const float4 r2 = *(const float4*)(s + (row + 2) * BSTR + bcol);

        a0 = a1 = a2 = a3 = 0.f;
#pragma unroll
        for (int rr = 0; rr < 3; rr++) {
            const float4 rv = (rr == 0) ? r0 : (rr == 1) ? r1 : r2;
            float f0 = __shfl_up_sync(0xffffffffu, rv.w, 1);
            float f5 = __shfl_down_sync(0xffffffffu, rv.x, 1);
            if (isL) f0 = ringL[rr];
            if (isR) f5 = ringR[rr];
            const float4 wa = w4[3 * rr + 0];
            const float4 wb = w4[3 * rr + 1];
            const float4 wc = w4[3 * rr + 2];
            a0 = fmaf(wa.x, f0,   fmaf(wb.x, rv.x, fmaf(wc.x, rv.y, a0)));
            a1 = fmaf(wa.y, rv.x, fmaf(wb.y, rv.y, fmaf(wc.y, rv.z, a1)));
            a2 = fmaf(wa.z, rv.y, fmaf(wb.z, rv.z, fmaf(wc.z, rv.w, a2)));
            a3 = fmaf(wa.w, rv.z, fmaf(wb.w, rv.w, fmaf(wc.w, f5,   a3)));
        }
        c0 = a0; c1 = a1; c2 = a2; c3 = a3;
        if (t < TFUSE - 1) {
            *(float4*)(buf[cur ^ 1] + (row + 1) * BSTR + bcol) =
                make_float4(a0, a1, a2, a3);     // STS.128
            __syncthreads();
        }
        cur ^= 1;
    }

    // ---- final: inner 40x48 straight from registers (STG.128) ----
    if (row >= OFF && row < OFF + TILE_Y && grp >= 2 && grp < 12) {
        float* out = fout + (size_t)b * PLANE;
        *(float4*)(out + gy * WW + gx0) = make_float4(c0, c1, c2, c3);
    }
}

// ---------------------------------------------------------------------------
extern "C" void kernel_launch(void* const* d_in, const int* in_sizes, int n_in,
                              void* d_out, int out_size) {
    const float* affinity = (const float*)d_in[0];
    const float* feature  = (const float*)d_in[1];
    float* out = (float*)d_out;

    void* p0 = nullptr; void* p1 = nullptr;
    cudaGetSymbolAddress(&p0, g_buf0);
    cudaGetSymbolAddress(&p1, g_buf1);
    float* buf[2] = { (float*)p0, (float*)p1 };

    dim3 fblk(NTHREADS, 1, 1);
    dim3 fgrd(WW / TILE_X, HH / TILE_Y, BATCH);   // 16 x 10 x 8

    const float* cursrc = feature;
    for (int l = 0; l < NLAUNCH; l++) {
        float* dst = (l == NLAUNCH - 1) ? out : buf[l & 1];
        fused_kernel<<<fgrd, fblk>>>(affinity, cursrc, dst);
        cursrc = dst;
    }
    (void)in_sizes; (void)n_in; (void)out_size;
}